// round 1
// baseline (speedup 1.0000x reference)
#include <cuda_runtime.h>
#include <cstdint>

#define BATCH 1024
#define TT    20
#define HH    768
#define G4    3072   // 4*H
#define DIN   4

// ---------------- scratch (static __device__, no allocs) ----------------
__device__ float g_evsum[32];
__device__ float g_hsum[32];
__device__ float g_rowsum[TT * G4];
__device__ float g_bsum[TT * G4];
__device__ float g_gates[BATCH * G4];   // step-0 gates scratch (12 MB)
__device__ float g_c[BATCH * HH];       // cell state after step 0
__device__ float g_h[BATCH * HH];       // final hidden state
__device__ unsigned g_bar_count;
__device__ volatile unsigned g_bar_sense;

// ---------------- activations (accurate fast-math) ----------------
__device__ __forceinline__ float fsig(float x) {
    return __fdividef(1.0f, 1.0f + __expf(-x));
}
__device__ __forceinline__ float ftanh(float x) {
    return 2.0f * fsig(2.0f * x) - 1.0f;
}

// ---------------- init ----------------
__global__ void init_kernel() {
    if (threadIdx.x < 32) { g_evsum[threadIdx.x] = 0.f; g_hsum[threadIdx.x] = 0.f; }
    if (threadIdx.x == 0) { g_bar_count = 0; g_bar_sense = 0; }
}

// ---------------- evsum[t] = sum over (b,h) of batch_event[:,t,:], t=1..19 ----------------
__global__ void evsum_kernel(const float* __restrict__ ev) {
    int warp  = (blockIdx.x * blockDim.x + threadIdx.x) >> 5;
    int lane  = threadIdx.x & 31;
    int nwarp = (gridDim.x * blockDim.x) >> 5;
    for (int r = warp; r < BATCH * TT; r += nwarp) {
        int t = r % TT;
        if (t == 0) continue;                 // t=0 handled by the GEMM directly
        const float* p = ev + (size_t)r * HH;
        float s = 0.f;
        #pragma unroll 4
        for (int k = lane; k < HH; k += 32) s += p[k];
        #pragma unroll
        for (int o = 16; o; o >>= 1) s += __shfl_down_sync(0xffffffffu, s, o);
        if (lane == 0) atomicAdd(&g_evsum[t], s);
    }
}

// ---------------- rowsum[t][j] = sum_k W_hh[t][j][k];  bsum = b_ih + b_hh ----------------
__global__ void rowsum_kernel(const float* __restrict__ whh,
                              const float* __restrict__ bih,
                              const float* __restrict__ bhh) {
    int warp  = (blockIdx.x * blockDim.x + threadIdx.x) >> 5;
    int lane  = threadIdx.x & 31;
    int nwarp = (gridDim.x * blockDim.x) >> 5;
    // rows t*G4+j for t = 1..19
    for (int rr = G4 + warp; rr < TT * G4; rr += nwarp) {
        const float* p = whh + (size_t)rr * HH;
        float s = 0.f;
        #pragma unroll 4
        for (int k = lane; k < HH; k += 32) s += p[k];
        #pragma unroll
        for (int o = 16; o; o >>= 1) s += __shfl_down_sync(0xffffffffu, s, o);
        if (lane == 0) {
            g_rowsum[rr] = s;
            g_bsum[rr]   = bih[rr] + bhh[rr];
        }
    }
}

// ---------------- step-0 GEMM: gates = ev0 @ Whh0^T + x0 @ Wih0^T + b ----------------
#define BM 128
#define BN 128
#define BK 8
__global__ __launch_bounds__(256, 1) void gemm0_kernel(
    const float* __restrict__ ev, const float* __restrict__ whh,
    const float* __restrict__ price, const float* __restrict__ wih,
    const float* __restrict__ bih, const float* __restrict__ bhh) {
    __shared__ float As[BK][BM + 4];
    __shared__ float Bs[BK][BN + 4];
    const int tid = threadIdx.x;
    const int bm = blockIdx.y * BM;
    const int bn = blockIdx.x * BN;
    const int tx = tid & 15, ty = tid >> 4;
    const int lr = tid >> 1;            // load row within tile (0..127)
    const int lk = (tid & 1) * 4;       // k sub-offset (0 or 4)

    float acc[8][8];
    #pragma unroll
    for (int i = 0; i < 8; i++)
        #pragma unroll
        for (int j = 0; j < 8; j++) acc[i][j] = 0.f;

    const size_t evStride = (size_t)TT * HH;   // row stride of batch_event at t=0
    for (int k0 = 0; k0 < HH; k0 += BK) {
        float4 a = *(const float4*)(ev + (size_t)(bm + lr) * evStride + k0 + lk);
        As[lk + 0][lr] = a.x; As[lk + 1][lr] = a.y;
        As[lk + 2][lr] = a.z; As[lk + 3][lr] = a.w;
        float4 b = *(const float4*)(whh + (size_t)(bn + lr) * HH + k0 + lk);
        Bs[lk + 0][lr] = b.x; Bs[lk + 1][lr] = b.y;
        Bs[lk + 2][lr] = b.z; Bs[lk + 3][lr] = b.w;
        __syncthreads();
        #pragma unroll
        for (int kk = 0; kk < BK; kk++) {
            float ar[8], br[8];
            #pragma unroll
            for (int i = 0; i < 8; i++) ar[i] = As[kk][ty * 8 + i];
            #pragma unroll
            for (int j = 0; j < 8; j++) br[j] = Bs[kk][tx * 8 + j];
            #pragma unroll
            for (int i = 0; i < 8; i++)
                #pragma unroll
                for (int j = 0; j < 8; j++) acc[i][j] += ar[i] * br[j];
        }
        __syncthreads();
    }

    // epilogue: + x0@Wih0^T + biases, store gates
    #pragma unroll
    for (int i = 0; i < 8; i++) {
        int m = bm + ty * 8 + i;
        float4 xp = *(const float4*)(price + (size_t)m * TT * DIN);  // price[m,0,:]
        #pragma unroll
        for (int j = 0; j < 8; j++) {
            int n = bn + tx * 8 + j;
            float4 wn = *(const float4*)(wih + (size_t)n * DIN);     // Wih[0,n,:]
            float g = acc[i][j]
                    + xp.x * wn.x + xp.y * wn.y + xp.z * wn.z + xp.w * wn.w
                    + bih[n] + bhh[n];
            g_gates[(size_t)m * G4 + n] = g;
        }
    }
}

// ---------------- step-0 pointwise: c1, hsum0 ----------------
__global__ void pw0_kernel() {
    __shared__ float sred[8];
    int idx = blockIdx.x * blockDim.x + threadIdx.x;   // exactly B*H threads
    int b = idx / HH;
    int h = idx - b * HH;
    const float* gr = g_gates + (size_t)b * G4;
    float gi = gr[h], gf_ = gr[h + HH], gg = gr[h + 2 * HH], go = gr[h + 3 * HH];
    (void)gf_;                                          // c0 == 0 => f-gate term vanishes
    float c = fsig(gi) * ftanh(gg);
    g_c[idx] = c;
    float hv = fsig(go) * ftanh(c);

    // block reduce hv -> g_hsum[0]
    #pragma unroll
    for (int o = 16; o; o >>= 1) hv += __shfl_down_sync(0xffffffffu, hv, o);
    int lane = threadIdx.x & 31, wid = threadIdx.x >> 5;
    if (lane == 0) sred[wid] = hv;
    __syncthreads();
    if (wid == 0) {
        float v = (lane < 8) ? sred[lane] : 0.f;
        #pragma unroll
        for (int o = 4; o; o >>= 1) v += __shfl_down_sync(0xffffffffu, v, o);
        if (lane == 0) atomicAdd(&g_hsum[0], v);
    }
}

// ---------------- persistent sequential kernel: steps 1..19 ----------------
#define NB 148
#define NT 256
#define TOTTH (NB * NT)   // 37888
#define CPT 21            // 37888*21 = 795648 >= 786432

__device__ __forceinline__ void grid_barrier(unsigned phase) {
    __syncthreads();
    if (threadIdx.x == 0) {
        __threadfence();
        unsigned v = atomicAdd(&g_bar_count, 1u);
        if (v == phase * NB - 1) {
            g_bar_sense = phase;            // release
        } else {
            while (g_bar_sense < phase) { }
        }
    }
    __syncthreads();
}

__global__ __launch_bounds__(NT, 1) void seq_kernel(const float* __restrict__ price,
                                                    const float* __restrict__ wih) {
    __shared__ float sred[NT / 32];
    const int tid = blockIdx.x * NT + threadIdx.x;
    const int cells = BATCH * HH;

    float c[CPT];
    #pragma unroll
    for (int k = 0; k < CPT; k++) {
        int cell = tid + k * TOTTH;
        c[k] = (cell < cells) ? g_c[cell] : 0.f;
    }

    for (int t = 1; t < TT; t++) {
        float hx = g_evsum[t] + ((volatile float*)g_hsum)[t - 1];
        float hloc = 0.f;
        #pragma unroll
        for (int k = 0; k < CPT; k++) {
            int cell = tid + k * TOTTH;
            if (cell < cells) {
                int b = cell / HH;
                int h = cell - b * HH;
                float4 x = *(const float4*)(price + ((size_t)b * TT + t) * DIN);
                int row = t * G4 + h;
                float4 wi = *(const float4*)(wih + (size_t)row * DIN);
                float4 wf = *(const float4*)(wih + (size_t)(row + HH) * DIN);
                float4 wg = *(const float4*)(wih + (size_t)(row + 2 * HH) * DIN);
                float4 wo = *(const float4*)(wih + (size_t)(row + 3 * HH) * DIN);
                float gi = x.x*wi.x + x.y*wi.y + x.z*wi.z + x.w*wi.w + g_bsum[row]          + hx * g_rowsum[row];
                float gf = x.x*wf.x + x.y*wf.y + x.z*wf.z + x.w*wf.w + g_bsum[row + HH]     + hx * g_rowsum[row + HH];
                float gg = x.x*wg.x + x.y*wg.y + x.z*wg.z + x.w*wg.w + g_bsum[row + 2*HH]   + hx * g_rowsum[row + 2*HH];
                float go = x.x*wo.x + x.y*wo.y + x.z*wo.z + x.w*wo.w + g_bsum[row + 3*HH]   + hx * g_rowsum[row + 3*HH];
                float ct = fsig(gf) * c[k] + fsig(gi) * ftanh(gg);
                c[k] = ct;
                float hv = fsig(go) * ftanh(ct);
                hloc += hv;
                if (t == TT - 1) g_h[cell] = hv;
            }
        }
        // block reduce hloc -> g_hsum[t]
        #pragma unroll
        for (int o = 16; o; o >>= 1) hloc += __shfl_down_sync(0xffffffffu, hloc, o);
        int lane = threadIdx.x & 31, wid = threadIdx.x >> 5;
        if (lane == 0) sred[wid] = hloc;
        __syncthreads();
        if (wid == 0) {
            float v = (lane < NT / 32) ? sred[lane] : 0.f;
            #pragma unroll
            for (int o = 4; o; o >>= 1) v += __shfl_down_sync(0xffffffffu, v, o);
            if (lane == 0) atomicAdd(&g_hsum[t], v);
        }
        if (t < TT - 1) grid_barrier((unsigned)t);
    }
}

// ---------------- output: out[b] = h[b,:] . fc_w + fc_b ----------------
__global__ void fc_kernel(const float* __restrict__ fcw, const float* __restrict__ fcb,
                          float* __restrict__ out) {
    __shared__ float sred[8];
    int b = blockIdx.x;
    float s = 0.f;
    for (int h = threadIdx.x; h < HH; h += blockDim.x)
        s += g_h[(size_t)b * HH + h] * fcw[h];
    #pragma unroll
    for (int o = 16; o; o >>= 1) s += __shfl_down_sync(0xffffffffu, s, o);
    int lane = threadIdx.x & 31, wid = threadIdx.x >> 5;
    if (lane == 0) sred[wid] = s;
    __syncthreads();
    if (wid == 0) {
        float v = (lane < 8) ? sred[lane] : 0.f;
        #pragma unroll
        for (int o = 4; o; o >>= 1) v += __shfl_down_sync(0xffffffffu, v, o);
        if (lane == 0) out[b] = v + fcb[0];
    }
}

// ---------------- launch ----------------
extern "C" void kernel_launch(void* const* d_in, const int* in_sizes, int n_in,
                              void* d_out, int out_size) {
    const float* price = (const float*)d_in[0];   // (B,T,4)
    const float* ev    = (const float*)d_in[1];   // (B,T,H)
    const float* wih   = (const float*)d_in[2];   // (T,4H,4)
    const float* whh   = (const float*)d_in[3];   // (T,4H,H)
    const float* bih   = (const float*)d_in[4];   // (T,4H)
    const float* bhh   = (const float*)d_in[5];   // (T,4H)
    const float* fcw   = (const float*)d_in[6];   // (1,H)
    const float* fcb   = (const float*)d_in[7];   // (1,)
    float* out = (float*)d_out;                    // (B,1)
    (void)in_sizes; (void)n_in; (void)out_size;

    init_kernel<<<1, 32>>>();
    evsum_kernel<<<296, 256>>>(ev);
    rowsum_kernel<<<592, 256>>>(whh, bih, bhh);
    dim3 gg(G4 / BN, BATCH / BM);
    gemm0_kernel<<<gg, 256>>>(ev, whh, price, wih, bih, bhh);
    pw0_kernel<<<(BATCH * HH) / 256, 256>>>();
    seq_kernel<<<NB, NT>>>(price, wih);
    fc_kernel<<<BATCH, 256>>>(fcw, fcb, out);
}

// round 3
// speedup vs baseline: 1.0109x; 1.0109x over previous
#include <cuda_runtime.h>
#include <cstdint>

#define BATCH 1024
#define TT    20
#define HH    768
#define G4    3072   // 4*H
#define DIN   4

// ---------------- scratch (static __device__, no allocs) ----------------
__device__ float g_evsum[32];
__device__ float g_hsum[32];
__device__ float g_rowsum[TT * G4];
__device__ float g_bsum[TT * G4];
__device__ float g_gates[BATCH * G4];   // step-0 raw GEMM output (i,g,o rows only)
__device__ float g_c[HH * BATCH];       // TRANSPOSED: [h][b]
__device__ float g_h[HH * BATCH];       // TRANSPOSED: [h][b]
__device__ unsigned g_bar_count;
__device__ volatile unsigned g_bar_sense;

// ---------------- activations (accurate fast-math, proven 7e-6 rel err) ----------------
__device__ __forceinline__ float fsig(float x) {
    return __fdividef(1.0f, 1.0f + __expf(-x));
}
__device__ __forceinline__ float ftanh(float x) {
    return 2.0f * fsig(2.0f * x) - 1.0f;
}
__device__ __forceinline__ uint32_t to_tf32_bits(float x) {
    float r; asm("cvt.rna.tf32.f32 %0, %1;" : "=f"(r) : "f"(x));
    return __float_as_uint(r);
}

// ---------------- init ----------------
__global__ void init_kernel() {
    if (threadIdx.x < 32) { g_evsum[threadIdx.x] = 0.f; g_hsum[threadIdx.x] = 0.f; }
    if (threadIdx.x == 0) { g_bar_count = 0; g_bar_sense = 0; }
}

// ---------------- evsum[t] = sum over (b,h) of batch_event[:,t,:], t=1..19 ----------------
__global__ void evsum_kernel(const float* __restrict__ ev) {
    int warp  = (blockIdx.x * blockDim.x + threadIdx.x) >> 5;
    int lane  = threadIdx.x & 31;
    int nwarp = (gridDim.x * blockDim.x) >> 5;
    for (int r = warp; r < BATCH * TT; r += nwarp) {
        int t = r % TT;
        if (t == 0) continue;
        const float* p = ev + (size_t)r * HH;
        float s = 0.f;
        #pragma unroll 4
        for (int k = lane; k < HH; k += 32) s += p[k];
        #pragma unroll
        for (int o = 16; o; o >>= 1) s += __shfl_down_sync(0xffffffffu, s, o);
        if (lane == 0) atomicAdd(&g_evsum[t], s);
    }
}

// ---------------- rowsum[t][j] = sum_k W_hh[t][j][k];  bsum = b_ih + b_hh (t>=1) ----------------
__global__ void rowsum_kernel(const float* __restrict__ whh,
                              const float* __restrict__ bih,
                              const float* __restrict__ bhh) {
    int warp  = (blockIdx.x * blockDim.x + threadIdx.x) >> 5;
    int lane  = threadIdx.x & 31;
    int nwarp = (gridDim.x * blockDim.x) >> 5;
    for (int rr = G4 + warp; rr < TT * G4; rr += nwarp) {
        const float* p = whh + (size_t)rr * HH;
        float s = 0.f;
        #pragma unroll 4
        for (int k = lane; k < HH; k += 32) s += p[k];
        #pragma unroll
        for (int o = 16; o; o >>= 1) s += __shfl_down_sync(0xffffffffu, s, o);
        if (lane == 0) {
            g_rowsum[rr] = s;
            g_bsum[rr]   = bih[rr] + bhh[rr];
        }
    }
}

// ---------------- step-0 GEMM via mma.sync tf32 ----------------
// gates[m, n] = ev[m,0,:] . whh[0,n,:]   for n in gates {i, g, o} only (f is dead: c0=0)
// CTA tile 128(M) x 128(N=one gate's h-block) x K-chunks of 32. 8 warps, 64x32 each.
#define BM 128
#define BN 128
#define BK 32
#define APAD 4
#define ASTR (BK + APAD)   // 36 floats -> 144B row stride (16B aligned)

__constant__ int c_gatesel[3] = {0, 2, 3};

__device__ __forceinline__ void mma_tf32(float* d, const uint32_t* a, const uint32_t* b) {
    asm volatile(
        "mma.sync.aligned.m16n8k8.row.col.f32.tf32.tf32.f32 "
        "{%0,%1,%2,%3}, {%4,%5,%6,%7}, {%8,%9}, {%0,%1,%2,%3};"
        : "+f"(d[0]), "+f"(d[1]), "+f"(d[2]), "+f"(d[3])
        : "r"(a[0]), "r"(a[1]), "r"(a[2]), "r"(a[3]), "r"(b[0]), "r"(b[1]));
}

__global__ __launch_bounds__(256, 1) void gemm0_kernel(
    const float* __restrict__ ev, const float* __restrict__ whh) {
    __shared__ float As[BM * ASTR];
    __shared__ float Bs[BN * ASTR];
    const int tid  = threadIdx.x;
    const int wid  = tid >> 5, lane = tid & 31;
    const int grp  = lane >> 2, tig = lane & 3;
    const int gate = c_gatesel[blockIdx.x / 6];
    const int hn   = (blockIdx.x % 6) * BN;
    const int bm   = blockIdx.y * BM;
    const int wm   = (wid >> 2) * 64;    // warp M offset (0 or 64)
    const int wn   = (wid & 3) * 32;     // warp N offset (0..96)

    float acc[4][4][4];
    #pragma unroll
    for (int i = 0; i < 4; i++)
        #pragma unroll
        for (int j = 0; j < 4; j++)
            #pragma unroll
            for (int r = 0; r < 4; r++) acc[i][j][r] = 0.f;

    const size_t evStride = (size_t)TT * HH;
    for (int k0 = 0; k0 < HH; k0 += BK) {
        __syncthreads();
        #pragma unroll
        for (int i = 0; i < 4; i++) {
            const int lin = tid + i * 256;
            const int row = lin >> 3;
            const int q   = (lin & 7) * 4;
            float4 a = *(const float4*)(ev + (size_t)(bm + row) * evStride + k0 + q);
            uint4 at; at.x = to_tf32_bits(a.x); at.y = to_tf32_bits(a.y);
                      at.z = to_tf32_bits(a.z); at.w = to_tf32_bits(a.w);
            *(uint4*)(As + row * ASTR + q) = at;
            float4 b = *(const float4*)(whh + (size_t)(gate * HH + hn + row) * HH + k0 + q);
            uint4 bt; bt.x = to_tf32_bits(b.x); bt.y = to_tf32_bits(b.y);
                      bt.z = to_tf32_bits(b.z); bt.w = to_tf32_bits(b.w);
            *(uint4*)(Bs + row * ASTR + q) = bt;
        }
        __syncthreads();
        #pragma unroll
        for (int kk = 0; kk < 4; kk++) {
            const int k8 = kk * 8;
            uint32_t af[4][4];
            #pragma unroll
            for (int mi = 0; mi < 4; mi++) {
                const float* ar = As + (wm + mi * 16) * ASTR + k8;
                af[mi][0] = __float_as_uint(ar[grp * ASTR + tig]);
                af[mi][1] = __float_as_uint(ar[(grp + 8) * ASTR + tig]);
                af[mi][2] = __float_as_uint(ar[grp * ASTR + tig + 4]);
                af[mi][3] = __float_as_uint(ar[(grp + 8) * ASTR + tig + 4]);
            }
            #pragma unroll
            for (int ni = 0; ni < 4; ni++) {
                const float* br = Bs + (wn + ni * 8 + grp) * ASTR + k8;
                uint32_t bf[2];
                bf[0] = __float_as_uint(br[tig]);
                bf[1] = __float_as_uint(br[tig + 4]);
                #pragma unroll
                for (int mi = 0; mi < 4; mi++)
                    mma_tf32(acc[mi][ni], af[mi], bf);
            }
        }
    }

    // store raw gates (coalesced float2 per thread)
    const int ncolbase = gate * HH + hn + wn;
    #pragma unroll
    for (int mi = 0; mi < 4; mi++) {
        #pragma unroll
        for (int ni = 0; ni < 4; ni++) {
            const int col = ncolbase + ni * 8 + 2 * tig;
            const int m0  = bm + wm + mi * 16 + grp;
            *(float2*)(g_gates + (size_t)m0 * G4 + col) =
                make_float2(acc[mi][ni][0], acc[mi][ni][1]);
            *(float2*)(g_gates + (size_t)(m0 + 8) * G4 + col) =
                make_float2(acc[mi][ni][2], acc[mi][ni][3]);
        }
    }
}

// ---------------- step-0 pointwise: c1 (transposed), hsum[0] ----------------
__global__ void pw0_kernel(const float* __restrict__ price, const float* __restrict__ wih,
                           const float* __restrict__ bih, const float* __restrict__ bhh) {
    __shared__ float sred[8];
    const int idx = blockIdx.x * blockDim.x + threadIdx.x;   // b*HH + h
    const int b = idx / HH;
    const int h = idx - b * HH;
    float4 xp = *(const float4*)(price + (size_t)b * TT * DIN);
    const int ni = h, ng = 2 * HH + h, no = 3 * HH + h;
    float4 wi = *(const float4*)(wih + (size_t)ni * DIN);
    float4 wg = *(const float4*)(wih + (size_t)ng * DIN);
    float4 wo = *(const float4*)(wih + (size_t)no * DIN);
    const float* gr = g_gates + (size_t)b * G4;
    float gi = gr[ni] + xp.x*wi.x + xp.y*wi.y + xp.z*wi.z + xp.w*wi.w + bih[ni] + bhh[ni];
    float gg = gr[ng] + xp.x*wg.x + xp.y*wg.y + xp.z*wg.z + xp.w*wg.w + bih[ng] + bhh[ng];
    float go = gr[no] + xp.x*wo.x + xp.y*wo.y + xp.z*wo.z + xp.w*wo.w + bih[no] + bhh[no];
    float c = fsig(gi) * ftanh(gg);           // c0 == 0 -> f-gate vanishes
    g_c[(size_t)h * BATCH + b] = c;
    float hv = fsig(go) * ftanh(c);

    #pragma unroll
    for (int o = 16; o; o >>= 1) hv += __shfl_down_sync(0xffffffffu, hv, o);
    int lane = threadIdx.x & 31, wid = threadIdx.x >> 5;
    if (lane == 0) sred[wid] = hv;
    __syncthreads();
    if (wid == 0) {
        float v = (lane < 8) ? sred[lane] : 0.f;
        #pragma unroll
        for (int o = 4; o; o >>= 1) v += __shfl_down_sync(0xffffffffu, v, o);
        if (lane == 0) atomicAdd(&g_hsum[0], v);
    }
}

// ---------------- persistent sequential kernel: steps 1..19 ----------------
#define NB 148
#define NT 256
#define TOTTH (NB * NT)   // 37888 = 37*1024: b fixed per thread, h warp-uniform
#define CPT 21

__device__ __forceinline__ void grid_barrier(unsigned phase) {
    __syncthreads();
    if (threadIdx.x == 0) {
        __threadfence();
        unsigned v = atomicAdd(&g_bar_count, 1u);
        if (v == phase * NB - 1) {
            g_bar_sense = phase;
        } else {
            while (g_bar_sense < phase) { }
        }
    }
    __syncthreads();
}

__global__ __launch_bounds__(NT, 1) void seq_kernel(const float* __restrict__ price,
                                                    const float* __restrict__ wih) {
    __shared__ float sred[NT / 32];
    const int tid = blockIdx.x * NT + threadIdx.x;
    const int b   = tid & 1023;          // constant per thread
    const int t0  = tid >> 10;           // 0..36, warp-uniform

    float c[CPT];
    #pragma unroll
    for (int k = 0; k < CPT; k++) {
        int h = t0 + 37 * k;
        c[k] = (h < HH) ? g_c[((size_t)h << 10) + b] : 0.f;   // coalesced
    }

    for (int t = 1; t < TT; t++) {
        float hx = g_evsum[t] + ((volatile float*)g_hsum)[t - 1];
        float4 x = *(const float4*)(price + ((size_t)b * TT + t) * DIN);
        float hloc = 0.f;
        #pragma unroll
        for (int k = 0; k < CPT; k++) {
            int h = t0 + 37 * k;
            if (h < HH) {
                int row = t * G4 + h;    // warp-uniform -> broadcast loads
                float4 wi = *(const float4*)(wih + (size_t)row * DIN);
                float4 wf = *(const float4*)(wih + (size_t)(row + HH) * DIN);
                float4 wg = *(const float4*)(wih + (size_t)(row + 2 * HH) * DIN);
                float4 wo = *(const float4*)(wih + (size_t)(row + 3 * HH) * DIN);
                float gi = x.x*wi.x + x.y*wi.y + x.z*wi.z + x.w*wi.w + g_bsum[row]          + hx * g_rowsum[row];
                float gf = x.x*wf.x + x.y*wf.y + x.z*wf.z + x.w*wf.w + g_bsum[row + HH]     + hx * g_rowsum[row + HH];
                float gg = x.x*wg.x + x.y*wg.y + x.z*wg.z + x.w*wg.w + g_bsum[row + 2*HH]   + hx * g_rowsum[row + 2*HH];
                float go = x.x*wo.x + x.y*wo.y + x.z*wo.z + x.w*wo.w + g_bsum[row + 3*HH]   + hx * g_rowsum[row + 3*HH];
                float ct = fsig(gf) * c[k] + fsig(gi) * ftanh(gg);
                c[k] = ct;
                float hv = fsig(go) * ftanh(ct);
                hloc += hv;
                if (t == TT - 1) g_h[((size_t)h << 10) + b] = hv;
            }
        }
        #pragma unroll
        for (int o = 16; o; o >>= 1) hloc += __shfl_down_sync(0xffffffffu, hloc, o);
        int lane = threadIdx.x & 31, wid = threadIdx.x >> 5;
        if (lane == 0) sred[wid] = hloc;
        __syncthreads();
        if (wid == 0) {
            float v = (lane < NT / 32) ? sred[lane] : 0.f;
            #pragma unroll
            for (int o = 4; o; o >>= 1) v += __shfl_down_sync(0xffffffffu, v, o);
            if (lane == 0) atomicAdd(&g_hsum[t], v);
        }
        if (t < TT - 1) grid_barrier((unsigned)t);
    }
}

// ---------------- output: out[b] = sum_h h[h][b]*fcw[h] + fc_b ----------------
__global__ void fc_kernel(const float* __restrict__ fcw, const float* __restrict__ fcb,
                          float* __restrict__ out) {
    __shared__ float part[8][32];
    const int b0 = blockIdx.x * 32;
    const int lane = threadIdx.x & 31, w = threadIdx.x >> 5;
    float s = 0.f;
    #pragma unroll 4
    for (int h = w; h < HH; h += 8)
        s += g_h[((size_t)h << 10) + b0 + lane] * fcw[h];   // coalesced
    part[w][lane] = s;
    __syncthreads();
    if (w == 0) {
        float v = part[0][lane] + part[1][lane] + part[2][lane] + part[3][lane]
                + part[4][lane] + part[5][lane] + part[6][lane] + part[7][lane];
        out[b0 + lane] = v + fcb[0];
    }
}

// ---------------- launch ----------------
extern "C" void kernel_launch(void* const* d_in, const int* in_sizes, int n_in,
                              void* d_out, int out_size) {
    const float* price = (const float*)d_in[0];   // (B,T,4)
    const float* ev    = (const float*)d_in[1];   // (B,T,H)
    const float* wih   = (const float*)d_in[2];   // (T,4H,4)
    const float* whh   = (const float*)d_in[3];   // (T,4H,H)
    const float* bih   = (const float*)d_in[4];   // (T,4H)
    const float* bhh   = (const float*)d_in[5];   // (T,4H)
    const float* fcw   = (const float*)d_in[6];   // (1,H)
    const float* fcb   = (const float*)d_in[7];   // (1,)
    float* out = (float*)d_out;                    // (B,1)
    (void)in_sizes; (void)n_in; (void)out_size;

    init_kernel<<<1, 32>>>();
    evsum_kernel<<<296, 256>>>(ev);
    rowsum_kernel<<<592, 256>>>(whh, bih, bhh);
    gemm0_kernel<<<dim3(18, BATCH / BM), 256>>>(ev, whh);
    pw0_kernel<<<(BATCH * HH) / 256, 256>>>(price, wih, bih, bhh);
    seq_kernel<<<NB, NT>>>(price, wih);
    fc_kernel<<<BATCH / 32, 256>>>(fcw, fcb, out);
}

// round 5
// speedup vs baseline: 1.3082x; 1.2941x over previous
#include <cuda_runtime.h>
#include <cstdint>

#define BATCH 1024
#define TT    20
#define HH    768
#define G4    3072   // 4*H
#define DIN   4

// ---------------- scratch (static __device__, no allocs) ----------------
__device__ float g_evsum[32];
__device__ float g_hsum[32];
__device__ float g_rowsum[TT * G4];
__device__ float g_bsum[TT * G4];
__device__ float g_gatesT[3 * HH * BATCH];  // step-0 gates, TRANSPOSED [gate(i,g,o)][h][b]
__device__ float g_h[HH * BATCH];           // final hidden state [h][b]
__device__ unsigned g_bar_count;
__device__ volatile unsigned g_bar_sense;

__constant__ int c_g3row[3] = {0, 2, 3};    // live gates at t=0 (f is dead: c0=0)

// ---------------- activations: HW tanh (MUFU.TANH) ----------------
__device__ __forceinline__ float htanh(float x) {
    float r; asm("tanh.approx.f32 %0, %1;" : "=f"(r) : "f"(x)); return r;
}
__device__ __forceinline__ float fsig(float x) {
    return fmaf(0.5f, htanh(0.5f * x), 0.5f);
}
__device__ __forceinline__ uint32_t to_tf32_bits(float x) {
    float r; asm("cvt.rna.tf32.f32 %0, %1;" : "=f"(r) : "f"(x));
    return __float_as_uint(r);
}

// ---------------- init ----------------
__global__ void init_kernel() {
    if (threadIdx.x < 32) { g_evsum[threadIdx.x] = 0.f; g_hsum[threadIdx.x] = 0.f; }
    if (threadIdx.x == 0) { g_bar_count = 0; g_bar_sense = 0; }
}

// ---------------- evsum[t] = sum over (b,h) of batch_event[:,t,:], t=1..19 ----------------
__global__ void evsum_kernel(const float* __restrict__ ev) {
    int warp  = (blockIdx.x * blockDim.x + threadIdx.x) >> 5;
    int lane  = threadIdx.x & 31;
    int nwarp = (gridDim.x * blockDim.x) >> 5;
    for (int r = warp; r < BATCH * TT; r += nwarp) {
        int t = r % TT;
        if (t == 0) continue;
        const float* p = ev + (size_t)r * HH;
        float s = 0.f;
        #pragma unroll 4
        for (int k = lane; k < HH; k += 32) s += p[k];
        #pragma unroll
        for (int o = 16; o; o >>= 1) s += __shfl_down_sync(0xffffffffu, s, o);
        if (lane == 0) atomicAdd(&g_evsum[t], s);
    }
}

// ---------------- rowsum[t][j] = sum_k W_hh[t][j][k];  bsum = b_ih + b_hh (t>=1) ----------------
__global__ void rowsum_kernel(const float* __restrict__ whh,
                              const float* __restrict__ bih,
                              const float* __restrict__ bhh) {
    int warp  = (blockIdx.x * blockDim.x + threadIdx.x) >> 5;
    int lane  = threadIdx.x & 31;
    int nwarp = (gridDim.x * blockDim.x) >> 5;
    for (int rr = G4 + warp; rr < TT * G4; rr += nwarp) {
        const float* p = whh + (size_t)rr * HH;
        float s = 0.f;
        #pragma unroll 4
        for (int k = lane; k < HH; k += 32) s += p[k];
        #pragma unroll
        for (int o = 16; o; o >>= 1) s += __shfl_down_sync(0xffffffffu, s, o);
        if (lane == 0) {
            g_rowsum[rr] = s;
            g_bsum[rr]   = bih[rr] + bhh[rr];
        }
    }
}

// ---------------- step-0 GEMM via mma.sync tf32 (gates i,g,o only; f dead) ----------------
#define BM 128
#define BN 128
#define BK 32
#define APAD 4
#define ASTR (BK + APAD)

__device__ __forceinline__ void mma_tf32(float* d, const uint32_t* a, const uint32_t* b) {
    asm volatile(
        "mma.sync.aligned.m16n8k8.row.col.f32.tf32.tf32.f32 "
        "{%0,%1,%2,%3}, {%4,%5,%6,%7}, {%8,%9}, {%0,%1,%2,%3};"
        : "+f"(d[0]), "+f"(d[1]), "+f"(d[2]), "+f"(d[3])
        : "r"(a[0]), "r"(a[1]), "r"(a[2]), "r"(a[3]), "r"(b[0]), "r"(b[1]));
}

__global__ __launch_bounds__(256, 1) void gemm0_kernel(
    const float* __restrict__ ev, const float* __restrict__ whh) {
    __shared__ float As[BM * ASTR];
    __shared__ float Bs[BN * ASTR];
    const int tid  = threadIdx.x;
    const int wid  = tid >> 5, lane = tid & 31;
    const int grp  = lane >> 2, tig = lane & 3;
    const int gidx = blockIdx.x / 6;           // 0..2 -> gates {i,g,o}
    const int gate = c_g3row[gidx];
    const int hn   = (blockIdx.x % 6) * BN;
    const int bm   = blockIdx.y * BM;
    const int wm   = (wid >> 2) * 64;
    const int wn   = (wid & 3) * 32;

    float acc[4][4][4];
    #pragma unroll
    for (int i = 0; i < 4; i++)
        #pragma unroll
        for (int j = 0; j < 4; j++)
            #pragma unroll
            for (int r = 0; r < 4; r++) acc[i][j][r] = 0.f;

    const size_t evStride = (size_t)TT * HH;
    for (int k0 = 0; k0 < HH; k0 += BK) {
        __syncthreads();
        #pragma unroll
        for (int i = 0; i < 4; i++) {
            const int lin = tid + i * 256;
            const int row = lin >> 3;
            const int q   = (lin & 7) * 4;
            float4 a = *(const float4*)(ev + (size_t)(bm + row) * evStride + k0 + q);
            uint4 at; at.x = to_tf32_bits(a.x); at.y = to_tf32_bits(a.y);
                      at.z = to_tf32_bits(a.z); at.w = to_tf32_bits(a.w);
            *(uint4*)(As + row * ASTR + q) = at;
            float4 b = *(const float4*)(whh + (size_t)(gate * HH + hn + row) * HH + k0 + q);
            uint4 bt; bt.x = to_tf32_bits(b.x); bt.y = to_tf32_bits(b.y);
                      bt.z = to_tf32_bits(b.z); bt.w = to_tf32_bits(b.w);
            *(uint4*)(Bs + row * ASTR + q) = bt;
        }
        __syncthreads();
        #pragma unroll
        for (int kk = 0; kk < 4; kk++) {
            const int k8 = kk * 8;
            uint32_t af[4][4];
            #pragma unroll
            for (int mi = 0; mi < 4; mi++) {
                const float* ar = As + (wm + mi * 16) * ASTR + k8;
                af[mi][0] = __float_as_uint(ar[grp * ASTR + tig]);
                af[mi][1] = __float_as_uint(ar[(grp + 8) * ASTR + tig]);
                af[mi][2] = __float_as_uint(ar[grp * ASTR + tig + 4]);
                af[mi][3] = __float_as_uint(ar[(grp + 8) * ASTR + tig + 4]);
            }
            #pragma unroll
            for (int ni = 0; ni < 4; ni++) {
                const float* br = Bs + (wn + ni * 8 + grp) * ASTR + k8;
                uint32_t bf[2];
                bf[0] = __float_as_uint(br[tig]);
                bf[1] = __float_as_uint(br[tig + 4]);
                #pragma unroll
                for (int mi = 0; mi < 4; mi++)
                    mma_tf32(acc[mi][ni], af[mi], bf);
            }
        }
    }

    // store TRANSPOSED: g_gatesT[gidx][h][b]; 8 consecutive m per (col,grp-octet) = full 32B sectors
    float* gT = g_gatesT + (size_t)gidx * HH * BATCH;
    #pragma unroll
    for (int mi = 0; mi < 4; mi++) {
        const int m0 = bm + wm + mi * 16 + grp;
        #pragma unroll
        for (int ni = 0; ni < 4; ni++) {
            const int h0 = hn + wn + ni * 8 + 2 * tig;
            gT[(size_t)h0 * BATCH + m0]             = acc[mi][ni][0];
            gT[(size_t)(h0 + 1) * BATCH + m0]       = acc[mi][ni][1];
            gT[(size_t)h0 * BATCH + m0 + 8]         = acc[mi][ni][2];
            gT[(size_t)(h0 + 1) * BATCH + m0 + 8]   = acc[mi][ni][3];
        }
    }
}

// ---------------- persistent sequential kernel: steps 0..19 ----------------
#define NB 148
#define NT 256
#define TOTTH (NB * NT)   // 37888 = 37*1024: b fixed per thread, t0 uniform per block
#define CPT 21

__device__ __forceinline__ void grid_barrier(unsigned phase) {
    __syncthreads();
    if (threadIdx.x == 0) {
        __threadfence();
        unsigned v = atomicAdd(&g_bar_count, 1u);
        if (v == phase * NB - 1) {
            g_bar_sense = phase;
        } else {
            while (g_bar_sense < phase) { }
        }
    }
    __syncthreads();
}

__global__ __launch_bounds__(NT, 1) void seq_kernel(const float* __restrict__ price,
                                                    const float* __restrict__ wih,
                                                    const float* __restrict__ bih,
                                                    const float* __restrict__ bhh) {
    __shared__ float sc[4 * CPT];     // per-(gate,k) gate constants for current t
    __shared__ float sred[NT / 32];
    const int tid = blockIdx.x * NT + threadIdx.x;
    const int b   = tid & 1023;              // constant per thread
    const int t0  = blockIdx.x >> 2;         // uniform per block (0..36)
    const int lane = threadIdx.x & 31, wrp = threadIdx.x >> 5;

    float c[CPT];

    // ================= t = 0 (from gemm gates; c0 = 0 so f-gate dead) =================
    if (threadIdx.x < 3 * CPT) {
        const int g = threadIdx.x / CPT, k = threadIdx.x - g * CPT;
        const int h = t0 + 37 * k;
        if (h < HH) {
            const int row = c_g3row[g] * HH + h;    // t=0 rows
            sc[g * CPT + k] = bih[row] + bhh[row];
        }
    }
    __syncthreads();
    {
        float4 x = *(const float4*)(price + (size_t)b * TT * DIN);   // price[b,0,:]
        float hloc = 0.f;
        #pragma unroll
        for (int k = 0; k < CPT; k++) {
            const int h = t0 + 37 * k;
            if (h < HH) {
                const size_t base = ((size_t)h << 10) + b;
                float gi = g_gatesT[base];
                float gg = g_gatesT[(size_t)HH * BATCH + base];
                float go = g_gatesT[(size_t)2 * HH * BATCH + base];
                float4 wi = *(const float4*)(wih + (size_t)(h) * DIN);
                float4 wg = *(const float4*)(wih + (size_t)(2 * HH + h) * DIN);
                float4 wo = *(const float4*)(wih + (size_t)(3 * HH + h) * DIN);
                gi += x.x*wi.x + x.y*wi.y + x.z*wi.z + x.w*wi.w + sc[k];
                gg += x.x*wg.x + x.y*wg.y + x.z*wg.z + x.w*wg.w + sc[CPT + k];
                go += x.x*wo.x + x.y*wo.y + x.z*wo.z + x.w*wo.w + sc[2 * CPT + k];
                float cv = fsig(gi) * htanh(gg);
                c[k] = cv;
                hloc += fsig(go) * htanh(cv);
            } else c[k] = 0.f;
        }
        #pragma unroll
        for (int o = 16; o; o >>= 1) hloc += __shfl_down_sync(0xffffffffu, hloc, o);
        if (lane == 0) sred[wrp] = hloc;
        __syncthreads();
        if (wrp == 0) {
            float v = (lane < NT / 32) ? sred[lane] : 0.f;
            #pragma unroll
            for (int o = 4; o; o >>= 1) v += __shfl_down_sync(0xffffffffu, v, o);
            if (lane == 0) atomicAdd(&g_hsum[0], v);
        }
    }
    grid_barrier(1u);

    // ================= t = 1..19 =================
    for (int t = 1; t < TT; t++) {
        const float hx = g_evsum[t] + ((volatile float*)g_hsum)[t - 1];
        // cooperative gate constants: bsum + hx*rowsum, gates ordered i,f,g,o
        if (threadIdx.x < 4 * CPT) {
            const int g = threadIdx.x / CPT, k = threadIdx.x - g * CPT;
            const int h = t0 + 37 * k;
            if (h < HH) {
                const int row = t * G4 + g * HH + h;
                sc[threadIdx.x] = fmaf(hx, g_rowsum[row], g_bsum[row]);
            }
        }
        __syncthreads();
        float4 x = *(const float4*)(price + ((size_t)b * TT + t) * DIN);
        float hloc = 0.f;
        #pragma unroll
        for (int k = 0; k < CPT; k++) {
            const int h = t0 + 37 * k;
            if (h < HH) {
                const int row = t * G4 + h;     // warp-uniform -> broadcast loads
                float4 wi = *(const float4*)(wih + (size_t)row * DIN);
                float4 wf = *(const float4*)(wih + (size_t)(row + HH) * DIN);
                float4 wg = *(const float4*)(wih + (size_t)(row + 2 * HH) * DIN);
                float4 wo = *(const float4*)(wih + (size_t)(row + 3 * HH) * DIN);
                float gi = x.x*wi.x + x.y*wi.y + x.z*wi.z + x.w*wi.w + sc[k];
                float gf = x.x*wf.x + x.y*wf.y + x.z*wf.z + x.w*wf.w + sc[CPT + k];
                float gg = x.x*wg.x + x.y*wg.y + x.z*wg.z + x.w*wg.w + sc[2 * CPT + k];
                float go = x.x*wo.x + x.y*wo.y + x.z*wo.z + x.w*wo.w + sc[3 * CPT + k];
                float ct = fsig(gf) * c[k] + fsig(gi) * htanh(gg);
                c[k] = ct;
                float hv = fsig(go) * htanh(ct);
                hloc += hv;
                if (t == TT - 1) g_h[((size_t)h << 10) + b] = hv;
            }
        }
        #pragma unroll
        for (int o = 16; o; o >>= 1) hloc += __shfl_down_sync(0xffffffffu, hloc, o);
        if (lane == 0) sred[wrp] = hloc;
        __syncthreads();
        if (wrp == 0) {
            float v = (lane < NT / 32) ? sred[lane] : 0.f;
            #pragma unroll
            for (int o = 4; o; o >>= 1) v += __shfl_down_sync(0xffffffffu, v, o);
            if (lane == 0) atomicAdd(&g_hsum[t], v);
        }
        if (t < TT - 1) grid_barrier((unsigned)(t + 1));
    }
}

// ---------------- output: out[b] = sum_h h[h][b]*fcw[h] + fc_b ----------------
__global__ void fc_kernel(const float* __restrict__ fcw, const float* __restrict__ fcb,
                          float* __restrict__ out) {
    __shared__ float part[8][32];
    const int b0 = blockIdx.x * 32;
    const int lane = threadIdx.x & 31, w = threadIdx.x >> 5;
    float s = 0.f;
    #pragma unroll 4
    for (int h = w; h < HH; h += 8)
        s += g_h[((size_t)h << 10) + b0 + lane] * fcw[h];
    part[w][lane] = s;
    __syncthreads();
    if (w == 0) {
        float v = part[0][lane] + part[1][lane] + part[2][lane] + part[3][lane]
                + part[4][lane] + part[5][lane] + part[6][lane] + part[7][lane];
        out[b0 + lane] = v + fcb[0];
    }
}

// ---------------- launch ----------------
extern "C" void kernel_launch(void* const* d_in, const int* in_sizes, int n_in,
                              void* d_out, int out_size) {
    const float* price = (const float*)d_in[0];   // (B,T,4)
    const float* ev    = (const float*)d_in[1];   // (B,T,H)
    const float* wih   = (const float*)d_in[2];   // (T,4H,4)
    const float* whh   = (const float*)d_in[3];   // (T,4H,H)
    const float* bih   = (const float*)d_in[4];   // (T,4H)
    const float* bhh   = (const float*)d_in[5];   // (T,4H)
    const float* fcw   = (const float*)d_in[6];   // (1,H)
    const float* fcb   = (const float*)d_in[7];   // (1,)
    float* out = (float*)d_out;                    // (B,1)
    (void)in_sizes; (void)n_in; (void)out_size;

    init_kernel<<<1, 32>>>();
    evsum_kernel<<<296, 256>>>(ev);
    rowsum_kernel<<<592, 256>>>(whh, bih, bhh);
    gemm0_kernel<<<dim3(18, BATCH / BM), 256>>>(ev, whh);
    seq_kernel<<<NB, NT>>>(price, wih, bih, bhh);
    fc_kernel<<<BATCH / 32, 256>>>(fcw, fcb, out);
}

// round 6
// speedup vs baseline: 2.6285x; 2.0093x over previous
#include <cuda_runtime.h>
#include <cstdint>

#define BATCH 1024
#define TT    20
#define HH    768
#define G4    3072   // 4*H
#define DIN   4

// ---------------- scratch (static __device__, no allocs) ----------------
__device__ float  g_evsum[32];
__device__ float2 g_rb[TT * G4];            // (rowsum, bih+bhh) per row
__device__ float  g_gatesT[3 * HH * BATCH]; // step-0 gates, TRANSPOSED [gate(i,g,o)][h][b]
__device__ float  g_hpart[TT * 160];        // per-step per-block h partial sums
__device__ unsigned g_bar_count;
__device__ volatile unsigned g_bar_sense;

__constant__ int c_g3row[3] = {0, 2, 3};    // live gates at t=0 (f is dead: c0=0)

// ---------------- activations: HW tanh (MUFU.TANH) ----------------
__device__ __forceinline__ float htanh(float x) {
    float r; asm("tanh.approx.f32 %0, %1;" : "=f"(r) : "f"(x)); return r;
}
__device__ __forceinline__ float fsig(float x) {
    return fmaf(0.5f, htanh(0.5f * x), 0.5f);
}
__device__ __forceinline__ uint32_t to_tf32_bits(float x) {
    float r; asm("cvt.rna.tf32.f32 %0, %1;" : "=f"(r) : "f"(x));
    return __float_as_uint(r);
}
__device__ __forceinline__ float dot4(float4 x, float4 w) {
    return fmaf(x.x, w.x, fmaf(x.y, w.y, fmaf(x.z, w.z, x.w * w.w)));
}

// ---------------- init: counters, evsum, out = fc_b ----------------
__global__ void init_kernel(const float* __restrict__ fcb, float* __restrict__ out) {
    int t = blockIdx.x * blockDim.x + threadIdx.x;
    if (t < BATCH) out[t] = fcb[0];
    if (t < 32) g_evsum[t] = 0.f;
    if (t == 32) { g_bar_count = 0; g_bar_sense = 0; }
}

// ---------------- evsum[t] += sum of batch_event[:,t,:], t=1..19 ----------------
__global__ void evsum_kernel(const float* __restrict__ ev) {
    int warp  = (blockIdx.x * blockDim.x + threadIdx.x) >> 5;
    int lane  = threadIdx.x & 31;
    int nwarp = (gridDim.x * blockDim.x) >> 5;
    for (int r = warp; r < BATCH * TT; r += nwarp) {
        int t = r % TT;
        if (t == 0) continue;
        const float* p = ev + (size_t)r * HH;
        float s = 0.f;
        #pragma unroll
        for (int i = 0; i < 6; i++) {
            float4 v = *(const float4*)(p + i * 128 + lane * 4);
            s += (v.x + v.y) + (v.z + v.w);
        }
        #pragma unroll
        for (int o = 16; o; o >>= 1) s += __shfl_down_sync(0xffffffffu, s, o);
        if (lane == 0) atomicAdd(&g_evsum[t], s);
    }
}

// ---------------- g_rb[row] = (rowsum of W_hh, b_ih+b_hh), rows t>=1 ----------------
__global__ void rowsum_kernel(const float* __restrict__ whh,
                              const float* __restrict__ bih,
                              const float* __restrict__ bhh) {
    int warp  = (blockIdx.x * blockDim.x + threadIdx.x) >> 5;
    int lane  = threadIdx.x & 31;
    int nwarp = (gridDim.x * blockDim.x) >> 5;
    for (int rr = G4 + warp; rr < TT * G4; rr += nwarp) {
        const float* p = whh + (size_t)rr * HH;
        float s = 0.f;
        #pragma unroll
        for (int i = 0; i < 6; i++) {
            float4 v = *(const float4*)(p + i * 128 + lane * 4);
            s += (v.x + v.y) + (v.z + v.w);
        }
        #pragma unroll
        for (int o = 16; o; o >>= 1) s += __shfl_down_sync(0xffffffffu, s, o);
        if (lane == 0) g_rb[rr] = make_float2(s, bih[rr] + bhh[rr]);
    }
}

// ---------------- step-0 GEMM via mma.sync tf32 (gates i,g,o; f dead) ----------------
#define BM 128
#define BN 128
#define BK 32
#define APAD 4
#define ASTR (BK + APAD)
#define NCH (HH / BK)

__device__ __forceinline__ void mma_tf32(float* d, const uint32_t* a, const uint32_t* b) {
    asm volatile(
        "mma.sync.aligned.m16n8k8.row.col.f32.tf32.tf32.f32 "
        "{%0,%1,%2,%3}, {%4,%5,%6,%7}, {%8,%9}, {%0,%1,%2,%3};"
        : "+f"(d[0]), "+f"(d[1]), "+f"(d[2]), "+f"(d[3])
        : "r"(a[0]), "r"(a[1]), "r"(a[2]), "r"(a[3]), "r"(b[0]), "r"(b[1]));
}

__global__ __launch_bounds__(256, 1) void gemm0_kernel(
    const float* __restrict__ ev, const float* __restrict__ whh) {
    __shared__ float As[BM * ASTR];
    __shared__ float Bs[BN * ASTR];
    const int tid  = threadIdx.x;
    const int wid  = tid >> 5, lane = tid & 31;
    const int grp  = lane >> 2, tig = lane & 3;
    const int gidx = blockIdx.x / 6;
    const int gate = c_g3row[gidx];
    const int hn   = (blockIdx.x % 6) * BN;
    const int bm   = blockIdx.y * BM;
    const int wm   = (wid >> 2) * 64;
    const int wn   = (wid & 3) * 32;

    const int lrow = tid >> 3;          // 0..31 base row block (4 rows per thread set)
    const int lq   = (tid & 7) * 4;
    const size_t evStride = (size_t)TT * HH;

    float acc[4][4][4];
    #pragma unroll
    for (int i = 0; i < 4; i++)
        #pragma unroll
        for (int j = 0; j < 4; j++)
            #pragma unroll
            for (int r = 0; r < 4; r++) acc[i][j][r] = 0.f;

    float4 ra[4], rb_[4];
    // prefetch chunk 0
    #pragma unroll
    for (int i = 0; i < 4; i++) {
        const int row = lrow + i * 32;
        ra[i]  = *(const float4*)(ev + (size_t)(bm + row) * evStride + lq);
        rb_[i] = *(const float4*)(whh + (size_t)(gate * HH + hn + row) * HH + lq);
    }

    for (int chunk = 0; chunk < NCH; chunk++) {
        // store current regs -> smem (with tf32 convert)
        #pragma unroll
        for (int i = 0; i < 4; i++) {
            const int row = lrow + i * 32;
            uint4 at; at.x = to_tf32_bits(ra[i].x); at.y = to_tf32_bits(ra[i].y);
                      at.z = to_tf32_bits(ra[i].z); at.w = to_tf32_bits(ra[i].w);
            *(uint4*)(As + row * ASTR + lq) = at;
            uint4 bt; bt.x = to_tf32_bits(rb_[i].x); bt.y = to_tf32_bits(rb_[i].y);
                      bt.z = to_tf32_bits(rb_[i].z); bt.w = to_tf32_bits(rb_[i].w);
            *(uint4*)(Bs + row * ASTR + lq) = bt;
        }
        __syncthreads();
        // prefetch next chunk (overlaps with MMA below)
        if (chunk + 1 < NCH) {
            const int k0 = (chunk + 1) * BK;
            #pragma unroll
            for (int i = 0; i < 4; i++) {
                const int row = lrow + i * 32;
                ra[i]  = *(const float4*)(ev + (size_t)(bm + row) * evStride + k0 + lq);
                rb_[i] = *(const float4*)(whh + (size_t)(gate * HH + hn + row) * HH + k0 + lq);
            }
        }
        #pragma unroll
        for (int kk = 0; kk < 4; kk++) {
            const int k8 = kk * 8;
            uint32_t af[4][4];
            #pragma unroll
            for (int mi = 0; mi < 4; mi++) {
                const float* ar = As + (wm + mi * 16) * ASTR + k8;
                af[mi][0] = __float_as_uint(ar[grp * ASTR + tig]);
                af[mi][1] = __float_as_uint(ar[(grp + 8) * ASTR + tig]);
                af[mi][2] = __float_as_uint(ar[grp * ASTR + tig + 4]);
                af[mi][3] = __float_as_uint(ar[(grp + 8) * ASTR + tig + 4]);
            }
            #pragma unroll
            for (int ni = 0; ni < 4; ni++) {
                const float* br = Bs + (wn + ni * 8 + grp) * ASTR + k8;
                uint32_t bf[2];
                bf[0] = __float_as_uint(br[tig]);
                bf[1] = __float_as_uint(br[tig + 4]);
                #pragma unroll
                for (int mi = 0; mi < 4; mi++)
                    mma_tf32(acc[mi][ni], af[mi], bf);
            }
        }
        __syncthreads();
    }

    float* gT = g_gatesT + (size_t)gidx * HH * BATCH;
    #pragma unroll
    for (int mi = 0; mi < 4; mi++) {
        const int m0 = bm + wm + mi * 16 + grp;
        #pragma unroll
        for (int ni = 0; ni < 4; ni++) {
            const int h0 = hn + wn + ni * 8 + 2 * tig;
            gT[(size_t)h0 * BATCH + m0]           = acc[mi][ni][0];
            gT[(size_t)(h0 + 1) * BATCH + m0]     = acc[mi][ni][1];
            gT[(size_t)h0 * BATCH + m0 + 8]       = acc[mi][ni][2];
            gT[(size_t)(h0 + 1) * BATCH + m0 + 8] = acc[mi][ni][3];
        }
    }
}

// ---------------- persistent sequential kernel: steps 0..19 + fc ----------------
#define NB 148
#define NT 256
#define CPT 21

__device__ __forceinline__ void grid_barrier(unsigned phase) {
    __syncthreads();
    if (threadIdx.x == 0) {
        __threadfence();
        unsigned v = atomicAdd(&g_bar_count, 1u);
        if (v == phase * NB - 1) {
            g_bar_sense = phase;
        } else {
            while (g_bar_sense < phase) { }
        }
    }
    __syncthreads();
}

__global__ __launch_bounds__(NT, 1) void seq_kernel(const float* __restrict__ price,
                                                    const float* __restrict__ wih,
                                                    const float* __restrict__ bih,
                                                    const float* __restrict__ bhh,
                                                    const float* __restrict__ fcw,
                                                    float* __restrict__ out) {
    __shared__ float4 s_w[4 * CPT];
    __shared__ float2 s_rb2[4 * CPT];
    __shared__ float  s_gc[4 * CPT];
    __shared__ float  s_evs[TT];
    __shared__ float  s_red[NT / 32];
    __shared__ float  s_hx;
    __shared__ float  s_fcw[CPT];
    const int blk = blockIdx.x;
    const int tix = threadIdx.x;
    const int b   = (blk * NT + tix) & 1023;    // constant per thread
    const int t0  = blk >> 2;                   // uniform per block (0..36)
    const int lane = tix & 31, wrp = tix >> 5;

    float c[CPT];

    // ================= t = 0 =================
    if (tix < 4 * CPT) {
        const int g = tix / CPT, k = tix - g * CPT;
        const int h = t0 + 37 * k;
        if (h < HH) {
            const int row = g * HH + h;         // t = 0 rows
            s_gc[tix] = bih[row] + bhh[row];
            s_w[tix]  = *(const float4*)(wih + (size_t)row * DIN);
        }
    } else if (tix < 4 * CPT + TT) {
        const int t = tix - 4 * CPT;
        s_evs[t] = g_evsum[t];
    }
    __syncthreads();
    {
        float4 x = *(const float4*)(price + (size_t)b * TT * DIN);
        float hloc = 0.f;
        #pragma unroll
        for (int k = 0; k < CPT; k++) {
            const int h = t0 + 37 * k;
            if (h < HH) {
                const size_t base = ((size_t)h << 10) + b;
                float gi = g_gatesT[base]                        + dot4(x, s_w[k])           + s_gc[k];
                float gg = g_gatesT[(size_t)HH * BATCH + base]   + dot4(x, s_w[2 * CPT + k]) + s_gc[2 * CPT + k];
                float go = g_gatesT[(size_t)2 * HH * BATCH + base] + dot4(x, s_w[3 * CPT + k]) + s_gc[3 * CPT + k];
                float cv = fsig(gi) * htanh(gg);
                c[k] = cv;
                hloc += fsig(go) * htanh(cv);
            } else c[k] = 0.f;
        }
        #pragma unroll
        for (int o = 16; o; o >>= 1) hloc += __shfl_down_sync(0xffffffffu, hloc, o);
        if (lane == 0) s_red[wrp] = hloc;
        __syncthreads();
        if (tix == 0) {
            float v = 0.f;
            #pragma unroll
            for (int w = 0; w < NT / 32; w++) v += s_red[w];
            g_hpart[0 * NB + blk] = v;
            __threadfence();
        }
    }
    grid_barrier(1u);

    // ================= t = 1..19 =================
    for (int t = 1; t < TT; t++) {
        // parallel: hpart gather (tid<148) + weight/const staging (tid 148..231)
        float p = 0.f;
        if (tix < NB) p = g_hpart[(size_t)(t - 1) * NB + tix];
        if (tix >= 148 && tix < 148 + 4 * CPT) {
            const int j = tix - 148;
            const int g = j / CPT, k = j - g * CPT;
            const int h = t0 + 37 * k;
            if (h < HH) {
                const int row = t * G4 + g * HH + h;
                s_rb2[j] = g_rb[row];
                s_w[j]   = *(const float4*)(wih + (size_t)row * DIN);
            }
        } else if (t == TT - 1 && tix >= 232 && tix < 232 + CPT) {
            const int k = tix - 232;
            const int h = t0 + 37 * k;
            s_fcw[k] = (h < HH) ? fcw[h] : 0.f;
        }
        #pragma unroll
        for (int o = 16; o; o >>= 1) p += __shfl_down_sync(0xffffffffu, p, o);
        if (lane == 0) s_red[wrp] = p;
        __syncthreads();
        if (tix == 0) {
            float v = 0.f;
            #pragma unroll
            for (int w = 0; w < NT / 32; w++) v += s_red[w];
            s_hx = v + s_evs[t];
        }
        __syncthreads();
        if (tix < 4 * CPT)
            s_gc[tix] = fmaf(s_hx, s_rb2[tix].x, s_rb2[tix].y);
        __syncthreads();

        float4 x = *(const float4*)(price + ((size_t)b * TT + t) * DIN);
        float hloc = 0.f, floc = 0.f;
        #pragma unroll
        for (int k = 0; k < CPT; k++) {
            const int h = t0 + 37 * k;
            if (h < HH) {
                float gi = dot4(x, s_w[k])           + s_gc[k];
                float gf = dot4(x, s_w[CPT + k])     + s_gc[CPT + k];
                float gg = dot4(x, s_w[2 * CPT + k]) + s_gc[2 * CPT + k];
                float go = dot4(x, s_w[3 * CPT + k]) + s_gc[3 * CPT + k];
                float ct = fsig(gf) * c[k] + fsig(gi) * htanh(gg);
                c[k] = ct;
                float hv = fsig(go) * htanh(ct);
                if (t == TT - 1) floc = fmaf(hv, s_fcw[k], floc);
                else             hloc += hv;
            }
        }
        if (t == TT - 1) {
            atomicAdd(&out[b], floc);            // 37 adds per address
        } else {
            #pragma unroll
            for (int o = 16; o; o >>= 1) hloc += __shfl_down_sync(0xffffffffu, hloc, o);
            if (lane == 0) s_red[wrp] = hloc;
            __syncthreads();
            if (tix == 0) {
                float v = 0.f;
                #pragma unroll
                for (int w = 0; w < NT / 32; w++) v += s_red[w];
                g_hpart[(size_t)t * NB + blk] = v;
                __threadfence();
            }
            grid_barrier((unsigned)(t + 1));
        }
    }
}

// ---------------- launch ----------------
extern "C" void kernel_launch(void* const* d_in, const int* in_sizes, int n_in,
                              void* d_out, int out_size) {
    const float* price = (const float*)d_in[0];   // (B,T,4)
    const float* ev    = (const float*)d_in[1];   // (B,T,H)
    const float* wih   = (const float*)d_in[2];   // (T,4H,4)
    const float* whh   = (const float*)d_in[3];   // (T,4H,H)
    const float* bih   = (const float*)d_in[4];   // (T,4H)
    const float* bhh   = (const float*)d_in[5];   // (T,4H)
    const float* fcw   = (const float*)d_in[6];   // (1,H)
    const float* fcb   = (const float*)d_in[7];   // (1,)
    float* out = (float*)d_out;                    // (B,1)
    (void)in_sizes; (void)n_in; (void)out_size;

    init_kernel<<<4, 256>>>(fcb, out);
    evsum_kernel<<<296, 256>>>(ev);
    rowsum_kernel<<<592, 256>>>(whh, bih, bhh);
    gemm0_kernel<<<dim3(18, BATCH / BM), 256>>>(ev, whh);
    seq_kernel<<<NB, NT>>>(price, wih, bih, bhh, fcw, out);
}